// round 1
// baseline (speedup 1.0000x reference)
#include <cuda_runtime.h>

// DotInteraction: x [B=16384, F=64, D=128] fp32 -> upper-triangle gram [B, 2016] fp32.
// One CTA per batch. X tile (32KB) staged in smem twice:
//   sA: natural row order (i-side loads; lanes share ti -> broadcast)
//   sB: row r stored at slot ((r&7)<<3)|(r>>3)  (j-side loads; lanes differing in tj
//       read slots 1 apart = 528B apart -> conflict-free LDS.128)
// Each compute thread owns a 4(i) x 8(j) register tile; 72 such tiles cover the
// upper triangle of the 64x64 gram (14% redundant FMAs near the diagonal).

#define FF 64
#define DD 128
#define NPAIR 2016

constexpr int ROWSTRIDE = 132;                   // floats; 528B: mult of 16B, kills b-conflicts
constexpr int SMEM_FLOATS = 2 * FF * ROWSTRIDE;  // 16896 floats = 67584 B

__global__ void __launch_bounds__(128) dotint_kernel(const float* __restrict__ x,
                                                     float* __restrict__ out) {
    extern __shared__ float smem[];
    float* sA = smem;
    float* sB = smem + FF * ROWSTRIDE;

    const int b = blockIdx.x;
    const int tid = threadIdx.x;
    const float4* xg = reinterpret_cast<const float4*>(x + (size_t)b * FF * DD);

    // ---- load 2048 float4 (32KB), store twice ----
#pragma unroll
    for (int it = 0; it < 16; ++it) {
        int idx = tid + it * 128;        // 0..2047
        int r = idx >> 5;                // row 0..63 (32 float4 per row)
        int c = idx & 31;                // float4 column
        float4 v = xg[idx];
        *reinterpret_cast<float4*>(&sA[r * ROWSTRIDE + c * 4]) = v;
        int slot = ((r & 7) << 3) | (r >> 3);
        *reinterpret_cast<float4*>(&sB[slot * ROWSTRIDE + c * 4]) = v;
    }
    __syncthreads();

    if (tid >= 72) return;

    // ---- map tid -> (ti, tj): tile grid 16 x 8 over 64x64 gram, upper tiles only ----
    // tile (ti,tj) covers rows 4ti..4ti+3, cols 8tj..8tj+7; needed iff 8tj+7 > 4ti
    int ti = 0, tj = 0, rem = tid;
    for (;;) {
        int mn = (4 * ti + 1) >> 3;      // == max(0, ceil((4ti-6)/8))
        int cnt = 8 - mn;
        if (rem < cnt) { tj = mn + rem; break; }
        rem -= cnt;
        ++ti;
    }

    const float* aBase = sA + (4 * ti) * ROWSTRIDE;
    const float* bBase = sB + tj * ROWSTRIDE;    // row (8tj+c) lives at slot c*8+tj

    float acc[4][8];
#pragma unroll
    for (int r = 0; r < 4; ++r)
#pragma unroll
        for (int c = 0; c < 8; ++c) acc[r][c] = 0.0f;

#pragma unroll 4
    for (int k = 0; k < 32; ++k) {
        float4 a[4], bv[8];
#pragma unroll
        for (int r = 0; r < 4; ++r)
            a[r] = *reinterpret_cast<const float4*>(&aBase[r * ROWSTRIDE + k * 4]);
#pragma unroll
        for (int c = 0; c < 8; ++c)
            bv[c] = *reinterpret_cast<const float4*>(&bBase[(c * 8) * ROWSTRIDE + k * 4]);
#pragma unroll
        for (int r = 0; r < 4; ++r)
#pragma unroll
            for (int c = 0; c < 8; ++c) {
                acc[r][c] += a[r].x * bv[c].x;
                acc[r][c] += a[r].y * bv[c].y;
                acc[r][c] += a[r].z * bv[c].z;
                acc[r][c] += a[r].w * bv[c].w;
            }
    }

    // ---- write upper-triangle outputs: idx(i,j) = i*(127-i)/2 + (j-i-1) ----
    float* ob = out + (size_t)b * NPAIR;
#pragma unroll
    for (int r = 0; r < 4; ++r) {
        int i = 4 * ti + r;
        int rowoff = i * (2 * FF - i - 1) / 2 - i - 1;   // idx = rowoff + j
#pragma unroll
        for (int c = 0; c < 8; ++c) {
            int j = 8 * tj + c;
            if (j > i) ob[rowoff + j] = acc[r][c];
        }
    }
}

extern "C" void kernel_launch(void* const* d_in, const int* in_sizes, int n_in,
                              void* d_out, int out_size) {
    const float* x = (const float*)d_in[0];
    float* out = (float*)d_out;
    int nbatch = in_sizes[0] / (FF * DD);
    cudaFuncSetAttribute(dotint_kernel, cudaFuncAttributeMaxDynamicSharedMemorySize,
                         SMEM_FLOATS * (int)sizeof(float));
    dotint_kernel<<<nbatch, 128, SMEM_FLOATS * sizeof(float)>>>(x, out);
}

// round 3
// speedup vs baseline: 2.4790x; 2.4790x over previous
#include <cuda_runtime.h>
#include <cuda_bf16.h>
#include <cstdint>

// DotInteraction: x [16384, 64, 128] fp32 -> upper-tri gram [16384, 2016] fp32.
// tcgen05 is unavailable (harness PTX target is sm_103 w/o 'a' features), so use
// baseline-PTX tensor ops: mma.sync m16n8k16 bf16 + ldmatrix.
// Precision: x = hi + lo (bf16 each); D = Xh*Xh^T + Xh*Xl^T + Xl*Xh^T (fp32 accum).
// 2 batches per CTA, 256 threads. Warp w: batch w>>2, row-tile rt=w&3 (16 rows),
// col-tiles c in [2*rt, 8) (8 cols each) -> covers the upper triangle exactly.

#define FF 64
#define NPAIR 2016

constexpr int ROWB = 272;            // bytes per 64-row matrix row (256 + 16 pad: conflict-free ldmatrix)
constexpr int MATB = 64 * ROWB;      // 17408 B per matrix
constexpr int SM_H = 0;              // [H0][H1][L0][L1]
constexpr int SM_L = 2 * MATB;
constexpr int SM_TOTAL = 4 * MATB;   // 69632 B

__device__ __forceinline__ uint32_t smem_u32(const void* p) {
    uint32_t a;
    asm("{ .reg .u64 t; cvta.to.shared.u64 t, %1; cvt.u32.u64 %0, t; }" : "=r"(a) : "l"(p));
    return a;
}
__device__ __forceinline__ void ldsm_x4(uint32_t* r, uint32_t addr) {
    asm volatile("ldmatrix.sync.aligned.m8n8.x4.shared.b16 {%0,%1,%2,%3}, [%4];"
                 : "=r"(r[0]), "=r"(r[1]), "=r"(r[2]), "=r"(r[3]) : "r"(addr));
}
__device__ __forceinline__ void ldsm_x2(uint32_t* r, uint32_t addr) {
    asm volatile("ldmatrix.sync.aligned.m8n8.x2.shared.b16 {%0,%1}, [%2];"
                 : "=r"(r[0]), "=r"(r[1]) : "r"(addr));
}
__device__ __forceinline__ void mma_bf16(float* c, const uint32_t* a, const uint32_t* b) {
    asm volatile(
        "mma.sync.aligned.m16n8k16.row.col.f32.bf16.bf16.f32 "
        "{%0,%1,%2,%3}, {%4,%5,%6,%7}, {%8,%9}, {%0,%1,%2,%3};"
        : "+f"(c[0]), "+f"(c[1]), "+f"(c[2]), "+f"(c[3])
        : "r"(a[0]), "r"(a[1]), "r"(a[2]), "r"(a[3]), "r"(b[0]), "r"(b[1]));
}

// NC = number of col-tiles (8 - 2*rt). aH/aL: lane-resolved A addresses (k-step 0).
// bH/bL: lane-resolved B addresses for col-tile cmin (k-step 0).
template <int NC>
__device__ __forceinline__ void compute_rows(uint32_t aH, uint32_t aL,
                                             uint32_t bH, uint32_t bL,
                                             float* __restrict__ ob, int i0, int lid) {
    float acc[NC][4];
#pragma unroll
    for (int c = 0; c < NC; ++c)
#pragma unroll
        for (int e = 0; e < 4; ++e) acc[c][e] = 0.0f;

#pragma unroll
    for (int kk = 0; kk < 8; ++kk) {
        uint32_t ah[4], al[4];
        ldsm_x4(ah, aH + kk * 32);
        ldsm_x4(al, aL + kk * 32);
#pragma unroll
        for (int c = 0; c < NC; ++c) {
            uint32_t bh[2], bl[2];
            ldsm_x2(bh, bH + c * (8 * ROWB) + kk * 32);
            ldsm_x2(bl, bL + c * (8 * ROWB) + kk * 32);
            mma_bf16(acc[c], ah, bh);   // hh
            mma_bf16(acc[c], ah, bl);   // hl
            mma_bf16(acc[c], al, bh);   // lh
        }
    }

    // epilogue: thread t holds (row i0 + t/4 + 8*half, col j0 + 2*(t%4) + d)
    const int rbase = i0 + (lid >> 2);
    const int cbase = 2 * (lid & 3);
#pragma unroll
    for (int c = 0; c < NC; ++c) {
        const int j0 = 8 * (8 - NC + c) + cbase;
#pragma unroll
        for (int half = 0; half < 2; ++half) {
            const int i = rbase + 8 * half;
            const int rowoff = i * (2 * FF - i - 1) / 2 - i - 1;  // out idx = rowoff + j
#pragma unroll
            for (int d = 0; d < 2; ++d) {
                const int j = j0 + d;
                if (j > i) ob[rowoff + j] = acc[c][2 * half + d];
            }
        }
    }
}

__global__ void __launch_bounds__(256) dotint_mma_kernel(const float* __restrict__ x,
                                                         float* __restrict__ out) {
    extern __shared__ char smem[];
    const uint32_t sbase = smem_u32(smem);
    const int tid = threadIdx.x;
    const int lid = tid & 31;
    const int wid = tid >> 5;

    // ---- load 2 batches (4096 float4), split hi/lo bf16, store padded rows ----
    const float4* xg = reinterpret_cast<const float4*>(x) + (size_t)blockIdx.x * 4096;
#pragma unroll
    for (int it = 0; it < 16; ++it) {
        int idx = tid + it * 256;          // 0..4095
        int r = idx >> 5;                  // 0..127 (batch = r>>6, row = r&63)
        int k4 = (idx & 31) * 4;           // element col 0..124
        float4 v = xg[idx];

        __nv_bfloat16 h0 = __float2bfloat16(v.x);
        __nv_bfloat16 h1 = __float2bfloat16(v.y);
        __nv_bfloat16 h2 = __float2bfloat16(v.z);
        __nv_bfloat16 h3 = __float2bfloat16(v.w);
        __nv_bfloat16 l0 = __float2bfloat16(v.x - __bfloat162float(h0));
        __nv_bfloat16 l1 = __float2bfloat16(v.y - __bfloat162float(h1));
        __nv_bfloat16 l2 = __float2bfloat16(v.z - __bfloat162float(h2));
        __nv_bfloat16 l3 = __float2bfloat16(v.w - __bfloat162float(h3));

        __nv_bfloat162 hp0 = __halves2bfloat162(h0, h1);
        __nv_bfloat162 hp1 = __halves2bfloat162(h2, h3);
        __nv_bfloat162 lp0 = __halves2bfloat162(l0, l1);
        __nv_bfloat162 lp1 = __halves2bfloat162(l2, l3);

        int b = r >> 6, row = r & 63;
        int off = b * MATB + row * ROWB + k4 * 2;
        *reinterpret_cast<uint2*>(smem + SM_H + off) =
            make_uint2(*reinterpret_cast<uint32_t*>(&hp0), *reinterpret_cast<uint32_t*>(&hp1));
        *reinterpret_cast<uint2*>(smem + SM_L + off) =
            make_uint2(*reinterpret_cast<uint32_t*>(&lp0), *reinterpret_cast<uint32_t*>(&lp1));
    }
    __syncthreads();

    // ---- compute: warp w -> batch w>>2, row-tile rt = w&3 ----
    const int b = wid >> 2;
    const int rt = wid & 3;
    const int i0 = rt * 16;

    const uint32_t baseH = sbase + SM_H + b * MATB;
    const uint32_t baseL = sbase + SM_L + b * MATB;

    // A lane addr: row i0 + (l&15), k-half (l>>4)*8 elems (=16B)
    const uint32_t aoff = (uint32_t)(i0 + (lid & 15)) * ROWB + (uint32_t)(lid >> 4) * 16;
    // B lane addr (x2 uses lanes 0-15): row j0 + (l&7), k-half ((l>>3)&1)*16B
    const uint32_t boff = (uint32_t)(lid & 7) * ROWB + (uint32_t)((lid >> 3) & 1) * 16;
    const uint32_t bcmin = (uint32_t)(2 * rt) * (8 * ROWB);

    float* ob = out + ((size_t)blockIdx.x * 2 + b) * NPAIR;

    switch (rt) {
        case 0: compute_rows<8>(baseH + aoff, baseL + aoff,
                                baseH + boff + bcmin, baseL + boff + bcmin, ob, i0, lid); break;
        case 1: compute_rows<6>(baseH + aoff, baseL + aoff,
                                baseH + boff + bcmin, baseL + boff + bcmin, ob, i0, lid); break;
        case 2: compute_rows<4>(baseH + aoff, baseL + aoff,
                                baseH + boff + bcmin, baseL + boff + bcmin, ob, i0, lid); break;
        default: compute_rows<2>(baseH + aoff, baseL + aoff,
                                 baseH + boff + bcmin, baseL + boff + bcmin, ob, i0, lid); break;
    }
}

extern "C" void kernel_launch(void* const* d_in, const int* in_sizes, int n_in,
                              void* d_out, int out_size) {
    const float* x = (const float*)d_in[0];
    float* out = (float*)d_out;
    int nbatch = in_sizes[0] / (FF * 128);   // 16384
    cudaFuncSetAttribute(dotint_mma_kernel, cudaFuncAttributeMaxDynamicSharedMemorySize, SM_TOTAL);
    dotint_mma_kernel<<<nbatch / 2, 256, SM_TOTAL>>>(x, out);
}